// round 1
// baseline (speedup 1.0000x reference)
#include <cuda_runtime.h>

#define N_THETA 180
#define N_PHI   360

// Single double accumulator in device global memory (no allocations allowed).
__device__ double g_sum;

__global__ void zero_acc_kernel() { g_sum = 0.0; }

// Dense part: sum over ALL elements of -log1p(-p) = -ln2 * sum(log2(1-p)).
// HBM-bound streaming reduction, float4 loads with streaming hint.
__global__ void __launch_bounds__(256) dense_reduce_kernel(const float4* __restrict__ p4,
                                                           long n4,
                                                           const float* __restrict__ p_tail,
                                                           int n_tail) {
    float a0 = 0.f, a1 = 0.f, a2 = 0.f, a3 = 0.f;
    long idx    = (long)blockIdx.x * blockDim.x + threadIdx.x;
    long stride = (long)gridDim.x * blockDim.x;
    for (long i = idx; i < n4; i += stride) {
        float4 v = __ldcs(&p4[i]);
        a0 += __log2f(1.0f - v.x);
        a1 += __log2f(1.0f - v.y);
        a2 += __log2f(1.0f - v.z);
        a3 += __log2f(1.0f - v.w);
    }
    float s = (a0 + a1) + (a2 + a3);
    // tail elements (count < 4), handled by global thread 0
    if (idx == 0) {
        for (int i = 0; i < n_tail; i++) s += __log2f(1.0f - p_tail[i]);
    }
    // warp reduce
    #pragma unroll
    for (int o = 16; o > 0; o >>= 1) s += __shfl_down_sync(0xffffffffu, s, o);
    __shared__ float sh[8];
    int lane = threadIdx.x & 31, w = threadIdx.x >> 5;
    if (lane == 0) sh[w] = s;
    __syncthreads();
    if (w == 0) {
        s = (lane < (int)(blockDim.x >> 5)) ? sh[lane] : 0.0f;
        #pragma unroll
        for (int o = 4; o > 0; o >>= 1) s += __shfl_down_sync(0xffffffffu, s, o);
        if (lane == 0) {
            // convert log2 -> -ln(): multiply by -ln2
            atomicAdd(&g_sum, -0.6931471805599453 * (double)s);
        }
    }
}

// Sparse correction: for each (sample, channel), add sum_y y*(lq - lp)
// over the Gaussian label support (radius RAD). y = w/wsum with
// w = exp(-(di^2+dj^2)/2); wsum over in-grid window (matches reference
// normalization to ~1e-14 relative; tail mass beyond RAD is exp(-32)).
#define RAD 8
#define WIN (2 * RAD + 1)

__global__ void __launch_bounds__(32) correction_kernel(const float* __restrict__ probs,
                                                        const float* __restrict__ gt_u,
                                                        const float* __restrict__ gt_r) {
    int bc = blockIdx.x;          // 0 .. 2*B-1
    int b  = bc >> 1;
    int ch = bc & 1;
    const float* g = ch ? gt_r : gt_u;
    float vx = g[b * 3 + 0], vy = g[b * 3 + 1], vz = g[b * 3 + 2];

    const float PI  = 3.14159265358979323846f;
    const float TPI = 6.28318530717958647692f;
    float theta = acosf(fminf(fmaxf(vz, -1.0f), 1.0f));
    float phi   = atan2f(vy, vx);
    if (phi < 0.0f) phi += TPI;
    int ti = (int)(theta * ((float)N_THETA / PI));
    ti = min(max(ti, 0), N_THETA - 1);
    int pj = (int)(phi * ((float)N_PHI / TPI));
    pj = min(max(pj, 0), N_PHI - 1);

    const float* base = probs + (long)(b * 2 + ch) * (N_THETA * N_PHI);

    float wsum = 0.0f, term = 0.0f;
    for (int cell = threadIdx.x; cell < WIN * WIN; cell += 32) {
        int di = cell / WIN - RAD;
        int dj = cell % WIN - RAD;
        int t  = ti + di;
        int pp = pj + dj;
        if (t >= 0 && t < N_THETA && pp >= 0 && pp < N_PHI) {
            float w = expf(-0.5f * (float)(di * di + dj * dj));
            wsum += w;
            float p  = base[t * N_PHI + pp];
            float lp = __logf(p);
            float lq = __logf(1.0f - p);
            term += w * (lq - lp);
        }
    }
    // warp reduce both
    #pragma unroll
    for (int o = 16; o > 0; o >>= 1) {
        wsum += __shfl_down_sync(0xffffffffu, wsum, o);
        term += __shfl_down_sync(0xffffffffu, term, o);
    }
    if (threadIdx.x == 0) {
        atomicAdd(&g_sum, (double)(term / wsum));
    }
}

__global__ void finalize_kernel(float* __restrict__ out, int n, double inv_denom) {
    float v = (float)(g_sum * inv_denom);
    for (int i = threadIdx.x; i < n; i += blockDim.x) out[i] = v;
}

extern "C" void kernel_launch(void* const* d_in, const int* in_sizes, int n_in,
                              void* d_out, int out_size) {
    const float* probs = (const float*)d_in[0];   // (B, 2, 180, 360)
    const float* gt_u  = (const float*)d_in[1];   // (B, 3)
    const float* gt_r  = (const float*)d_in[2];   // (B, 3)
    float* out = (float*)d_out;

    long n  = (long)in_sizes[0];                  // B*2*180*360
    int  B  = (int)(n / (2L * N_THETA * N_PHI));
    long n4 = n >> 2;
    int  n_tail = (int)(n - (n4 << 2));

    zero_acc_kernel<<<1, 1>>>();

    // One full wave on 148 SMs: 1184 blocks x 256 threads (8 CTAs/SM).
    dense_reduce_kernel<<<1184, 256>>>((const float4*)probs, n4,
                                       probs + (n4 << 2), n_tail);

    correction_kernel<<<2 * B, 32>>>(probs, gt_u, gt_r);

    // loss = total_sum / (B * N_THETA * N_PHI)   (both channels share the denom)
    double denom = (double)B * (double)N_THETA * (double)N_PHI;
    finalize_kernel<<<1, 32>>>(out, out_size, 1.0 / denom);
}

// round 2
// speedup vs baseline: 1.2237x; 1.2237x over previous
#include <cuda_runtime.h>

#define N_THETA 180
#define N_PHI   360
#define NBLOCKS 1184
#define NTHREADS 256

// Device-global accumulator + completion counter (zero-initialized at load;
// the last block resets them each call so graph replays are deterministic).
__device__ double g_sum;
__device__ unsigned int g_done;

#define RAD 8
#define WIN (2 * RAD + 1)

__global__ void __launch_bounds__(NTHREADS)
fused_loss_kernel(const float4* __restrict__ p4, long n4,
                  const float* __restrict__ p_tail, int n_tail,
                  const float* __restrict__ probs,
                  const float* __restrict__ gt_u,
                  const float* __restrict__ gt_r,
                  int B2,                 // 2*B correction tasks
                  float* __restrict__ out, int out_n,
                  double inv_denom) {
    // ---------------- dense streaming reduction: sum log2(1-p) --------------
    float a0 = 0.f, a1 = 0.f, a2 = 0.f, a3 = 0.f;
    float b0 = 0.f, b1 = 0.f, b2 = 0.f, b3 = 0.f;
    long idx    = (long)blockIdx.x * NTHREADS + threadIdx.x;
    long stride = (long)NBLOCKS * NTHREADS;

    long i = idx;
    for (; i + stride < n4; i += 2 * stride) {
        float4 u = __ldcs(&p4[i]);
        float4 v = __ldcs(&p4[i + stride]);
        a0 += __log2f(1.0f - u.x);
        a1 += __log2f(1.0f - u.y);
        a2 += __log2f(1.0f - u.z);
        a3 += __log2f(1.0f - u.w);
        b0 += __log2f(1.0f - v.x);
        b1 += __log2f(1.0f - v.y);
        b2 += __log2f(1.0f - v.z);
        b3 += __log2f(1.0f - v.w);
    }
    if (i < n4) {
        float4 u = __ldcs(&p4[i]);
        a0 += __log2f(1.0f - u.x);
        a1 += __log2f(1.0f - u.y);
        a2 += __log2f(1.0f - u.z);
        a3 += __log2f(1.0f - u.w);
    }
    float s = ((a0 + a1) + (a2 + a3)) + ((b0 + b1) + (b2 + b3));
    if (idx == 0) {
        for (int t = 0; t < n_tail; t++) s += __log2f(1.0f - p_tail[t]);
    }
    // log2 -> -ln
    s *= -0.6931471805599453f;

    // warp reduce dense partial
    #pragma unroll
    for (int o = 16; o > 0; o >>= 1) s += __shfl_down_sync(0xffffffffu, s, o);

    // ---------------- sparse correction: one task per global warp -----------
    int lane = threadIdx.x & 31;
    int w    = threadIdx.x >> 5;
    int gwid = blockIdx.x * (NTHREADS / 32) + w;
    if (gwid < B2) {
        int b  = gwid >> 1;
        int ch = gwid & 1;
        const float* g = ch ? gt_r : gt_u;
        float vx = g[b * 3 + 0], vy = g[b * 3 + 1], vz = g[b * 3 + 2];

        const float PI  = 3.14159265358979323846f;
        const float TPI = 6.28318530717958647692f;
        float theta = acosf(fminf(fmaxf(vz, -1.0f), 1.0f));
        float phi   = atan2f(vy, vx);
        if (phi < 0.0f) phi += TPI;
        int ti = (int)(theta * ((float)N_THETA / PI));
        ti = min(max(ti, 0), N_THETA - 1);
        int pj = (int)(phi * ((float)N_PHI / TPI));
        pj = min(max(pj, 0), N_PHI - 1);

        const float* base = probs + (long)(b * 2 + ch) * (N_THETA * N_PHI);

        float wsum = 0.0f, term = 0.0f;
        for (int cell = lane; cell < WIN * WIN; cell += 32) {
            int di = cell / WIN - RAD;
            int dj = cell % WIN - RAD;
            int t  = ti + di;
            int pp = pj + dj;
            if (t >= 0 && t < N_THETA && pp >= 0 && pp < N_PHI) {
                float wg = expf(-0.5f * (float)(di * di + dj * dj));
                wsum += wg;
                float p  = base[t * N_PHI + pp];
                term += wg * (__logf(1.0f - p) - __logf(p));
            }
        }
        #pragma unroll
        for (int o = 16; o > 0; o >>= 1) {
            wsum += __shfl_down_sync(0xffffffffu, wsum, o);
            term += __shfl_down_sync(0xffffffffu, term, o);
        }
        if (lane == 0) s += term / wsum;
    }

    // ---------------- block reduce + single atomic per block ----------------
    __shared__ float sh[NTHREADS / 32];
    if (lane == 0) sh[w] = s;
    __syncthreads();
    if (w == 0) {
        s = (lane < NTHREADS / 32) ? sh[lane] : 0.0f;
        #pragma unroll
        for (int o = 4; o > 0; o >>= 1) s += __shfl_down_sync(0xffffffffu, s, o);
        if (lane == 0) {
            atomicAdd(&g_sum, (double)s);
            __threadfence();
            unsigned int done = atomicAdd(&g_done, 1u);
            if (done == NBLOCKS - 1) {
                // last block: finalize + reset for next graph replay
                __threadfence();
                double total = *((volatile double*)&g_sum);
                float v = (float)(total * inv_denom);
                for (int t = 0; t < out_n; t++) out[t] = v;
                g_sum  = 0.0;
                g_done = 0u;
            }
        }
    }
}

extern "C" void kernel_launch(void* const* d_in, const int* in_sizes, int n_in,
                              void* d_out, int out_size) {
    const float* probs = (const float*)d_in[0];   // (B, 2, 180, 360)
    const float* gt_u  = (const float*)d_in[1];   // (B, 3)
    const float* gt_r  = (const float*)d_in[2];   // (B, 3)
    float* out = (float*)d_out;

    long n  = (long)in_sizes[0];
    int  B  = (int)(n / (2L * N_THETA * N_PHI));
    long n4 = n >> 2;
    int  n_tail = (int)(n - (n4 << 2));

    double denom = (double)B * (double)N_THETA * (double)N_PHI;

    fused_loss_kernel<<<NBLOCKS, NTHREADS>>>(
        (const float4*)probs, n4, probs + (n4 << 2), n_tail,
        probs, gt_u, gt_r, 2 * B, out, out_size, 1.0 / denom);
}